// round 13
// baseline (speedup 1.0000x reference)
#include <cuda_runtime.h>
#include <cstdint>

#define NB      32
#define NCH     84
#define NCLS    80
#define NANCH   8400
#define NQUAD   2100          // NANCH / 4
#define NPART   4             // select partitions per batch
#define PARTN   (NANCH / NPART)   // 2100 keys per partition
#define TOPK    1000
#define MAXDET  300
#define GCAP    128
#define CONF    0.25f
#define IOU_THR 0.7f
#define MAX_WH  7680.0f
#define IMG_SZ  640.0f

// ---------------- scratch (device globals; no allocation allowed) ----------
__device__ unsigned long long g_key[NB * NANCH];     // (fmap(score)<<32)|~idx
__device__ int                g_label[NB * NANCH];
__device__ float              g_box[NB * NANCH * 4];
__device__ unsigned long long g_loc[NB * NPART * TOPK];  // partition winners

__constant__ int c_coco[80] = {
    1,2,3,4,5,6,7,8,9,10,11,13,14,15,16,17,18,19,20,21,22,23,24,25,27,28,
    31,32,33,34,35,36,37,38,39,40,41,42,43,44,46,47,48,49,50,51,52,53,54,55,
    56,57,58,59,60,61,62,63,64,65,67,70,72,73,74,75,76,77,78,79,80,81,82,84,
    85,86,87,88,89,90
};

__device__ __forceinline__ unsigned int fmap(float f) {
    unsigned int u = __float_as_uint(f);
    return (u & 0x80000000u) ? ~u : (u | 0x80000000u);
}
__device__ __forceinline__ float funmap(unsigned int u) {
    return (u & 0x80000000u) ? __uint_as_float(u ^ 0x80000000u)
                             : __uint_as_float(~u);
}

// ---------------- stage 1: decode (channel-split pairs, float4 quads) ------
__global__ void __launch_bounds__(256) decode_kernel(const float4* __restrict__ p4) {
    int t = blockIdx.x * blockDim.x + threadIdx.x;
    int pair = t >> 1;
    int half = t & 1;
    int b = blockIdx.y;
    bool valid = (pair < NQUAD);
    int g = valid ? pair : (NQUAD - 1);
    const float4* base = p4 + (size_t)b * (NCH * NQUAD) + g;
    const float4* cb   = base + (size_t)(4 + (half ? 40 : 0)) * NQUAD;

    float4 vx = base[0];
    float4 vy = base[NQUAD];
    float4 vw = base[2 * NQUAD];
    float4 vh = base[3 * NQUAD];

    float4 best = cb[0];
    int4   bi   = make_int4(0, 0, 0, 0);
#pragma unroll
    for (int c = 1; c < 40; c++) {
        float4 v = cb[(size_t)c * NQUAD];
        if (v.x > best.x) { best.x = v.x; bi.x = c; }
        if (v.y > best.y) { best.y = v.y; bi.y = c; }
        if (v.z > best.z) { best.z = v.z; bi.z = c; }
        if (v.w > best.w) { best.w = v.w; bi.w = c; }
    }

    const unsigned FULL = 0xFFFFFFFFu;
    float obx = __shfl_down_sync(FULL, best.x, 1);
    float oby = __shfl_down_sync(FULL, best.y, 1);
    float obz = __shfl_down_sync(FULL, best.z, 1);
    float obw = __shfl_down_sync(FULL, best.w, 1);
    int   oix = __shfl_down_sync(FULL, bi.x, 1);
    int   oiy = __shfl_down_sync(FULL, bi.y, 1);
    int   oiz = __shfl_down_sync(FULL, bi.z, 1);
    int   oiw = __shfl_down_sync(FULL, bi.w, 1);

    if (half == 0 && valid) {
        if (obx > best.x) { best.x = obx; bi.x = oix + 40; }
        if (oby > best.y) { best.y = oby; bi.y = oiy + 40; }
        if (obz > best.z) { best.z = obz; bi.z = oiz + 40; }
        if (obw > best.w) { best.w = obw; bi.w = oiw + 40; }

        int o = b * NANCH + 4 * g;

        float s0 = (best.x > CONF) ? best.x : -1.0f;
        float s1 = (best.y > CONF) ? best.y : -1.0f;
        float s2 = (best.z > CONF) ? best.z : -1.0f;
        float s3 = (best.w > CONF) ? best.w : -1.0f;

        unsigned long long k0 = ((unsigned long long)fmap(s0) << 32) | (unsigned int)(~(4*g+0));
        unsigned long long k1 = ((unsigned long long)fmap(s1) << 32) | (unsigned int)(~(4*g+1));
        unsigned long long k2 = ((unsigned long long)fmap(s2) << 32) | (unsigned int)(~(4*g+2));
        unsigned long long k3 = ((unsigned long long)fmap(s3) << 32) | (unsigned int)(~(4*g+3));
        ((ulonglong2*)g_key)[o/2]     = make_ulonglong2(k0, k1);
        ((ulonglong2*)g_key)[o/2 + 1] = make_ulonglong2(k2, k3);

        ((int4*)g_label)[b * NQUAD + g] = bi;

        float4* boxo = (float4*)g_box + o;
        {
            float x = vx.x * IMG_SZ, y = vy.x * IMG_SZ, hw = vw.x * IMG_SZ * 0.5f, hh = vh.x * IMG_SZ * 0.5f;
            boxo[0] = make_float4(x - hw, y - hh, x + hw, y + hh);
        }
        {
            float x = vx.y * IMG_SZ, y = vy.y * IMG_SZ, hw = vw.y * IMG_SZ * 0.5f, hh = vh.y * IMG_SZ * 0.5f;
            boxo[1] = make_float4(x - hw, y - hh, x + hw, y + hh);
        }
        {
            float x = vx.z * IMG_SZ, y = vy.z * IMG_SZ, hw = vw.z * IMG_SZ * 0.5f, hh = vh.z * IMG_SZ * 0.5f;
            boxo[2] = make_float4(x - hw, y - hh, x + hw, y + hh);
        }
        {
            float x = vx.w * IMG_SZ, y = vy.w * IMG_SZ, hw = vw.w * IMG_SZ * 0.5f, hh = vh.w * IMG_SZ * 0.5f;
            boxo[3] = make_float4(x - hw, y - hh, x + hw, y + hh);
        }
    }
}

// ---------------- shared radix top-K (exact, verified R10 machinery) --------
// Selects exactly TOPK largest distinct 64-bit keys from gsrc[0..n) into
// cand[0..TOPK) (unsorted). key/actl are smem scratch (key >= n, actl >= n).
struct SelShared {
    int (*hist)[2048];
    int* hfin;
    unsigned long long* s_prefix;
    int* s_k; int* s_cnt; int* s_actn;
};

__device__ void radix_select(const unsigned long long* __restrict__ gsrc, int n,
                             unsigned long long* key, unsigned long long* actl,
                             unsigned long long* cand, SelShared sh) {
    int tid = threadIdx.x, wid = tid >> 5, lane = tid & 31;
    const unsigned FULL = 0xFFFFFFFFu;
    unsigned lmask = (1u << lane) - 1u;

    if (tid == 0) { *sh.s_prefix = 0ull; *sh.s_k = TOPK; *sh.s_cnt = 0; *sh.s_actn = 0; }

    const int WD[5] = {11, 11, 10, 8, 8};
    const int SH[5] = {53, 42, 32, 8, 0};
    const int FS[5] = { 0, 53, 42, 16, 8};

#pragma unroll 1
    for (int pass = 0; pass < 5; ++pass) {
        int nb = 1 << WD[pass];
        for (int i = tid; i < 4 * 2048; i += 1024) ((int*)sh.hist)[i] = 0;
        __syncthreads();

        unsigned long long pfx = *sh.s_prefix;
        int shift = SH[pass], fs = FS[pass];
        unsigned mask = (unsigned)(nb - 1);
        const unsigned long long* arr = (pass == 1) ? key : actl;
        int nn = (pass < 2) ? n : *sh.s_actn;
        int iters = (nn + 1023) >> 10;
        int sub = wid & 3;

#pragma unroll 1
        for (int ii = 0; ii < iters; ++ii) {
            int i = tid + (ii << 10);
            unsigned long long v;
            if (pass == 0) {                       // merged load + histogram
                v = (i < n) ? gsrc[i] : 0ull;
                if (i < n) key[i] = v;
            } else {
                v = (i < nn) ? arr[i] : 0ull;
            }
            bool a = (i < nn) && ((pass == 0) || ((v >> fs) == pfx));
            int bin = (int)((unsigned)(v >> shift) & mask);
            unsigned am = __ballot_sync(FULL, a);
            if (am == FULL) {
                int b0 = __shfl_sync(FULL, bin, 0);
                if (__all_sync(FULL, bin == b0)) {
                    if (lane == 0) atomicAdd(&sh.hist[sub][b0], 32);
                    continue;
                }
            }
            if (a) atomicAdd(&sh.hist[sub][bin], 1);
        }
        __syncthreads();

        for (int bb = tid; bb < nb; bb += 1024)
            sh.hfin[bb] = sh.hist[0][bb] + sh.hist[1][bb] + sh.hist[2][bb] + sh.hist[3][bb];
        __syncthreads();

        if (tid < 32) {
            int bpl = nb >> 5;
            int base = lane * bpl;
            int tot = 0;
            for (int e = 0; e < bpl; ++e) tot += sh.hfin[base + e];
            int suf = tot;
#pragma unroll
            for (int o = 1; o < 32; o <<= 1) {
                int v2 = __shfl_down_sync(FULL, suf, o);
                if (lane + o < 32) suf += v2;
            }
            int S = suf - tot;
            int k = *sh.s_k;
            if (k > S && k <= S + tot) {
                int S2 = S;
                for (int e = bpl - 1; e >= 0; --e) {
                    int h = sh.hfin[base + e];
                    if (k <= S2 + h) {
                        unsigned long long np =
                            (*sh.s_prefix << WD[pass]) | (unsigned long long)(base + e);
                        if (pass == 2) np = (np << 16) | 0xFFFFull;  // ~idx high bits
                        *sh.s_prefix = np;
                        *sh.s_k = k - S2;
                        break;
                    }
                    S2 += h;
                }
            }
        }
        __syncthreads();

        if (pass == 1) {       // compact active set + gather sure winners
            unsigned long long p22 = *sh.s_prefix;
            int iters2 = (n + 1023) >> 10;
#pragma unroll 1
            for (int ii = 0; ii < iters2; ++ii) {
                int i = tid + (ii << 10);
                unsigned long long v = (i < n) ? key[i] : 0ull;
                unsigned long long hi = v >> 42;
                bool m  = (i < n) && (hi == p22);
                bool sw = (i < n) && (hi > p22);
                unsigned balm = __ballot_sync(FULL, m);
                if (balm) {
                    int base2 = 0;
                    if (lane == 0) base2 = atomicAdd(sh.s_actn, __popc(balm));
                    base2 = __shfl_sync(FULL, base2, 0);
                    if (m) actl[base2 + __popc(balm & lmask)] = v;
                }
                unsigned balw = __ballot_sync(FULL, sw);
                if (balw) {
                    int base2 = 0;
                    if (lane == 0) base2 = atomicAdd(sh.s_cnt, __popc(balw));
                    base2 = __shfl_sync(FULL, base2, 0);
                    if (sw) cand[base2 + __popc(balw & lmask)] = v;
                }
            }
            __syncthreads();
        }
    }

    // remaining winners from the small active set (exactly TOPK - s_cnt)
    {
        unsigned long long thr = *sh.s_prefix;
        int n2 = *sh.s_actn;
        int iters = (n2 + 1023) >> 10;
#pragma unroll 1
        for (int ii = 0; ii < iters; ++ii) {
            int i = tid + (ii << 10);
            unsigned long long v = (i < n2) ? actl[i] : 0ull;
            bool win = (i < n2) && (v >= thr);
            unsigned bal = __ballot_sync(FULL, win);
            if (bal) {
                int base2 = 0;
                if (lane == 0) base2 = atomicAdd(sh.s_cnt, __popc(bal));
                base2 = __shfl_sync(FULL, base2, 0);
                if (win) cand[base2 + __popc(bal & lmask)] = v;
            }
        }
    }
    __syncthreads();
}

// ---------------- stage 2: local top-1000 per 2100-key partition ------------
// Global top-1000 is contained in the union of partition top-1000s.
#define SMEM_LOC ((2112 + 2112 + 1024) * 8)

__global__ void __launch_bounds__(1024) local_select_kernel() {
    extern __shared__ unsigned long long sm[];
    unsigned long long* key  = sm;
    unsigned long long* actl = sm + 2112;
    unsigned long long* cand = sm + 4224;
    __shared__ int hist[4][2048];
    __shared__ int hfin[2048];
    __shared__ unsigned long long s_prefix;
    __shared__ int s_k, s_cnt, s_actn;

    int q = blockIdx.x, b = blockIdx.y;
    SelShared sh = { hist, hfin, &s_prefix, &s_k, &s_cnt, &s_actn };
    radix_select(g_key + b * NANCH + q * PARTN, PARTN, key, actl, cand, sh);

    int tid = threadIdx.x;
    if (tid < TOPK)
        g_loc[((size_t)b * NPART + q) * TOPK + tid] = cand[tid];
}

// ---------------- stage 3: merge + sort + per-label NMS + emit --------------
#define SMEM_MRG ((4096 + 4096 + 1024) * 8)

__global__ void __launch_bounds__(1024) merge_nms_kernel(float* __restrict__ out) {
    extern __shared__ unsigned long long sm[];
    unsigned long long* key  = sm;            // 4096
    unsigned long long* actl = sm + 4096;     // 4096
    unsigned long long* cand = sm + 8192;     // 1024

    // phase-B aliases over dead regions
    unsigned short* list   = (unsigned short*)key;              // 20KB
    unsigned int*   labmap = (unsigned int*)(key + 2560);       // 10KB
    float*          nx1  = (float*)actl;
    float*          ny1  = nx1 + TOPK;
    float*          nx2  = ny1 + TOPK;
    float*          ny2  = nx2 + TOPK;
    float*          nar  = ny2 + TOPK;

    __shared__ int hist[4][2048];
    __shared__ int hfin[2048];
    __shared__ unsigned long long s_prefix;
    __shared__ int s_k, s_cnt, s_actn;
    __shared__ unsigned int keepw[32];
    __shared__ int wtot[32], woff[32];

    int b = blockIdx.x, tid = threadIdx.x;
    int wid = tid >> 5, lane = tid & 31;
    const unsigned FULL = 0xFFFFFFFFu;
    unsigned lmask = (1u << lane) - 1u;

    float* ob = out + (size_t)b * MAXDET * 4;
    float* os = out + (size_t)NB * MAXDET * 4 + (size_t)b * MAXDET;
    float* ol = out + (size_t)NB * MAXDET * 5 + (size_t)b * MAXDET;

    SelShared sh = { hist, hfin, &s_prefix, &s_k, &s_cnt, &s_actn };
    radix_select(g_loc + (size_t)b * NPART * TOPK, NPART * TOPK, key, actl, cand, sh);

    if (tid < 1024 - TOPK) cand[TOPK + tid] = 0ull;
    __syncthreads();

    // register bitonic sort, descending; double-buffered smem stages
    unsigned long long r = (tid < TOPK) ? cand[tid] : 0ull;
    {
        unsigned long long* bufs[2] = { cand, actl };
        int cb = 0;
#pragma unroll 1
        for (int kk = 2; kk <= 1024; kk <<= 1) {
#pragma unroll 1
            for (int j = kk >> 1; j > 0; j >>= 1) {
                unsigned long long o;
                if (j >= 32) {
                    bufs[cb][tid] = r;
                    __syncthreads();
                    o = bufs[cb][tid ^ j];
                    cb ^= 1;
                } else {
                    o = __shfl_xor_sync(FULL, r, j);
                }
                bool up    = ((tid & kk) == 0);
                bool lower = ((tid & j) == 0);
                unsigned long long mx = (r > o) ? r : o;
                unsigned long long mn = (r > o) ? o : r;
                r = (up == lower) ? mx : mn;
            }
        }
    }
    __syncthreads();   // bufs reads done before phase-B aliases overwrite

    // ---------------- phase B: gather + per-label NMS + emit ----------------
    for (int t = tid; t < MAXDET; t += 1024) {
        ((float4*)ob)[t] = make_float4(0.f, 0.f, 0.f, 0.f);
        os[t] = 0.0f;
        ol[t] = 0.0f;
    }
    if (tid < 32) keepw[tid] = 0u;
    for (int i = tid; i < NCLS * 32; i += 1024) labmap[i] = 0u;

    int   src = 0, lb = 0;
    float sc  = 0.0f;
    if (tid < TOPK) {
        unsigned int idx = ~(unsigned int)(r & 0xFFFFFFFFull);
        src = b * NANCH + (int)idx;
        lb  = g_label[src];
        sc  = funmap((unsigned int)(r >> 32));
        float4 bx = ((const float4*)g_box)[src];
        float off = (float)lb * MAX_WH;
        float a0 = bx.x + off, a1 = bx.y + off, a2 = bx.z + off, a3 = bx.w + off;
        nx1[tid] = a0; ny1[tid] = a1; nx2[tid] = a2; ny2[tid] = a3;
        nar[tid] = (a2 - a0) * (a3 - a1);
    }
    __syncthreads();

    if (tid < TOPK)
        atomicOr(&labmap[lb * 32 + (tid >> 5)], 1u << (tid & 31));
    __syncthreads();
    if (tid < TOPK) {
        int w = tid >> 5;
        int rank = __popc(labmap[lb * 32 + w] & lmask);
        for (int ww = 0; ww < w; ++ww) rank += __popc(labmap[lb * 32 + ww]);
        if (rank < GCAP) list[lb * GCAP + rank] = (unsigned short)tid;
    }
    __syncthreads();

    const float HI = 0.7000007f;
    const float LO = 0.6999993f;

    for (int l = wid; l < NCLS; l += 32) {
        int myc = __popc(labmap[l * 32 + lane]);
#pragma unroll
        for (int o = 16; o > 0; o >>= 1)
            myc += __shfl_xor_sync(FULL, myc, o);
        int g = min(myc, GCAP);
        int base = l * GCAP;

        unsigned long long kept0 = 0ull, kept1 = 0ull;
#pragma unroll 1
        for (int m = 0; m < g; ++m) {
            int rm = list[base + m];
            float cx1 = nx1[rm], cy1 = ny1[rm], cx2 = nx2[rm], cy2 = ny2[rm];
            float ca  = nar[rm];
            bool sup = false;
#pragma unroll 1
            for (int bs = 0; bs < m; bs += 32) {
                int mi = bs + lane;
                bool valid = (mi < m) &&
                    (((mi < 64) ? (kept0 >> mi) : (kept1 >> (mi - 64))) & 1ull);
                bool s = false;
                if (valid) {
                    int ri = list[base + mi];
                    float lx = fmaxf(nx1[ri], cx1);
                    float ly = fmaxf(ny1[ri], cy1);
                    float rx = fminf(nx2[ri], cx2);
                    float ry = fminf(ny2[ri], cy2);
                    float wd = fmaxf(rx - lx, 0.0f);
                    float ht = fmaxf(ry - ly, 0.0f);
                    float inter = wd * ht;
                    float denom = nar[ri] + ca - inter + 1e-7f;
                    if (inter > HI * denom)       s = true;
                    else if (inter >= LO * denom) s = (inter / denom) > IOU_THR;
                }
                if (__ballot_sync(FULL, s)) { sup = true; break; }
            }
            if (!sup) {
                if (m < 64) kept0 |= 1ull << m; else kept1 |= 1ull << (m - 64);
                if (lane == 0) atomicOr(&keepw[rm >> 5], 1u << (rm & 31));
            }
        }
    }
    __syncthreads();

    // conf gate + block scan + scatter (kept are already score-descending)
    int f = 0;
    if (tid < TOPK)
        f = (int)((keepw[tid >> 5] >> (tid & 31)) & 1u) & (sc > CONF ? 1 : 0);
    unsigned bal = __ballot_sync(FULL, f);
    if (lane == 0) wtot[wid] = __popc(bal);
    __syncthreads();
    if (tid < 32) {
        int v = wtot[lane];
        int p = v;
#pragma unroll
        for (int o = 1; o < 32; o <<= 1) {
            int t2 = __shfl_up_sync(FULL, p, o);
            if (lane >= o) p += t2;
        }
        woff[lane] = p - v;
    }
    __syncthreads();
    int pos = woff[wid] + __popc(bal & lmask);

    if (f && pos < MAXDET) {
        ((float4*)ob)[pos] = ((const float4*)g_box)[src];
        os[pos] = sc;
        ol[pos] = (float)c_coco[lb];
    }
}

// ---------------- launch ----------------------------------------------------
extern "C" void kernel_launch(void* const* d_in, const int* in_sizes, int n_in,
                              void* d_out, int out_size) {
    (void)in_sizes; (void)n_in; (void)out_size;
    const float4* preds4 = (const float4*)d_in[0];
    float* out = (float*)d_out;

    cudaFuncSetAttribute(local_select_kernel,
                         cudaFuncAttributeMaxDynamicSharedMemorySize, SMEM_LOC);
    cudaFuncSetAttribute(merge_nms_kernel,
                         cudaFuncAttributeMaxDynamicSharedMemorySize, SMEM_MRG);

    dim3 dgrid((NQUAD * 2 + 255) / 256, NB);
    decode_kernel<<<dgrid, 256>>>(preds4);
    local_select_kernel<<<dim3(NPART, NB), 1024, SMEM_LOC>>>();
    merge_nms_kernel<<<NB, 1024, SMEM_MRG>>>(out);
}

// round 14
// speedup vs baseline: 1.4038x; 1.4038x over previous
#include <cuda_runtime.h>
#include <cstdint>

#define NB      32
#define NCH     84
#define NCLS    80
#define NANCH   8400
#define NQUAD   2100          // NANCH / 4
#define TOPK    1000
#define MAXDET  300
#define GCAP    128
#define CONF    0.25f
#define IOU_THR 0.7f
#define MAX_WH  7680.0f
#define IMG_SZ  640.0f

// ---------------- scratch (device globals; no allocation allowed) ----------
__device__ unsigned long long g_key  [NB * NANCH];   // (fmap(score)<<32)|~idx
__device__ int                g_label[NB * NANCH];
__device__ float              g_box  [NB * NANCH * 4];

__constant__ int c_coco[80] = {
    1,2,3,4,5,6,7,8,9,10,11,13,14,15,16,17,18,19,20,21,22,23,24,25,27,28,
    31,32,33,34,35,36,37,38,39,40,41,42,43,44,46,47,48,49,50,51,52,53,54,55,
    56,57,58,59,60,61,62,63,64,65,67,70,72,73,74,75,76,77,78,79,80,81,82,84,
    85,86,87,88,89,90
};

__device__ __forceinline__ unsigned int fmap(float f) {
    unsigned int u = __float_as_uint(f);
    return (u & 0x80000000u) ? ~u : (u | 0x80000000u);
}
__device__ __forceinline__ float funmap(unsigned int u) {
    return (u & 0x80000000u) ? __uint_as_float(u ^ 0x80000000u)
                             : __uint_as_float(~u);
}

// ---------------- stage 1: decode (channel-split pairs, float4 quads) ------
__global__ void __launch_bounds__(256) decode_kernel(const float4* __restrict__ p4) {
    int t = blockIdx.x * blockDim.x + threadIdx.x;
    int pair = t >> 1;
    int half = t & 1;
    int b = blockIdx.y;
    bool valid = (pair < NQUAD);
    int g = valid ? pair : (NQUAD - 1);
    const float4* base = p4 + (size_t)b * (NCH * NQUAD) + g;
    const float4* cb   = base + (size_t)(4 + (half ? 40 : 0)) * NQUAD;

    float4 vx = base[0];
    float4 vy = base[NQUAD];
    float4 vw = base[2 * NQUAD];
    float4 vh = base[3 * NQUAD];

    float4 best = cb[0];
    int4   bi   = make_int4(0, 0, 0, 0);
#pragma unroll
    for (int c = 1; c < 40; c++) {
        float4 v = cb[(size_t)c * NQUAD];
        if (v.x > best.x) { best.x = v.x; bi.x = c; }
        if (v.y > best.y) { best.y = v.y; bi.y = c; }
        if (v.z > best.z) { best.z = v.z; bi.z = c; }
        if (v.w > best.w) { best.w = v.w; bi.w = c; }
    }

    const unsigned FULL = 0xFFFFFFFFu;
    float obx = __shfl_down_sync(FULL, best.x, 1);
    float oby = __shfl_down_sync(FULL, best.y, 1);
    float obz = __shfl_down_sync(FULL, best.z, 1);
    float obw = __shfl_down_sync(FULL, best.w, 1);
    int   oix = __shfl_down_sync(FULL, bi.x, 1);
    int   oiy = __shfl_down_sync(FULL, bi.y, 1);
    int   oiz = __shfl_down_sync(FULL, bi.z, 1);
    int   oiw = __shfl_down_sync(FULL, bi.w, 1);

    if (half == 0 && valid) {
        if (obx > best.x) { best.x = obx; bi.x = oix + 40; }
        if (oby > best.y) { best.y = oby; bi.y = oiy + 40; }
        if (obz > best.z) { best.z = obz; bi.z = oiz + 40; }
        if (obw > best.w) { best.w = obw; bi.w = oiw + 40; }

        int o = b * NANCH + 4 * g;

        float s0 = (best.x > CONF) ? best.x : -1.0f;
        float s1 = (best.y > CONF) ? best.y : -1.0f;
        float s2 = (best.z > CONF) ? best.z : -1.0f;
        float s3 = (best.w > CONF) ? best.w : -1.0f;

        unsigned long long k0 = ((unsigned long long)fmap(s0) << 32) | (unsigned int)(~(4*g+0));
        unsigned long long k1 = ((unsigned long long)fmap(s1) << 32) | (unsigned int)(~(4*g+1));
        unsigned long long k2 = ((unsigned long long)fmap(s2) << 32) | (unsigned int)(~(4*g+2));
        unsigned long long k3 = ((unsigned long long)fmap(s3) << 32) | (unsigned int)(~(4*g+3));
        ((ulonglong2*)g_key)[o/2]     = make_ulonglong2(k0, k1);
        ((ulonglong2*)g_key)[o/2 + 1] = make_ulonglong2(k2, k3);

        ((int4*)g_label)[b * NQUAD + g] = bi;

        float4* boxo = (float4*)g_box + o;
        {
            float x = vx.x * IMG_SZ, y = vy.x * IMG_SZ, hw = vw.x * IMG_SZ * 0.5f, hh = vh.x * IMG_SZ * 0.5f;
            boxo[0] = make_float4(x - hw, y - hh, x + hw, y + hh);
        }
        {
            float x = vx.y * IMG_SZ, y = vy.y * IMG_SZ, hw = vw.y * IMG_SZ * 0.5f, hh = vh.y * IMG_SZ * 0.5f;
            boxo[1] = make_float4(x - hw, y - hh, x + hw, y + hh);
        }
        {
            float x = vx.z * IMG_SZ, y = vy.z * IMG_SZ, hw = vw.z * IMG_SZ * 0.5f, hh = vh.z * IMG_SZ * 0.5f;
            boxo[2] = make_float4(x - hw, y - hh, x + hw, y + hh);
        }
        {
            float x = vx.w * IMG_SZ, y = vy.w * IMG_SZ, hw = vw.w * IMG_SZ * 0.5f, hh = vh.w * IMG_SZ * 0.5f;
            boxo[3] = make_float4(x - hw, y - hh, x + hw, y + hh);
        }
    }
}

// ---------------- stage 2: fused 2-pass select + sort + NMS + emit ----------
// Pass 0+1 resolve the top 22 bits of the threshold key. Keys with 22-bit
// prefix > threshold-prefix are sure winners (each outranks every active
// key); keys == prefix are the active set. If sure+active <= 1024, the top
// 1000 of (sure U active U zero-pad) equals the exact global top-1000 — and
// we sort 1024 keys anyway, so radix passes 2-4 are skipped entirely.
// Fallback to the verified 5-pass path if the active set is too big.
#define SEL_SMEM ((8448 + 8448 + 1024) * 8)

__global__ void __launch_bounds__(1024) fused_kernel(float* __restrict__ out) {
    extern __shared__ unsigned long long sm[];
    unsigned long long* key  = sm;            // 8400 (8448 pad)
    unsigned long long* actl = sm + 8448;     // active set
    unsigned long long* cand = sm + 16896;    // 1024 winners

    // phase-B aliases over dead regions
    unsigned short* list   = (unsigned short*)key;              // 20KB
    unsigned int*   labmap = (unsigned int*)(key + 2560);       // 80*32 words
    float*          nx1  = (float*)actl;
    float*          ny1  = nx1 + TOPK;
    float*          nx2  = ny1 + TOPK;
    float*          ny2  = nx2 + TOPK;
    float*          nar  = ny2 + TOPK;

    __shared__ int hist[4][2048];
    __shared__ int hfin[2048];
    __shared__ unsigned long long s_prefix;
    __shared__ int s_k, s_cnt, s_actn;
    __shared__ unsigned int keepw[32];
    __shared__ int wtot[32], woff[32];

    int b = blockIdx.x, tid = threadIdx.x;
    int wid = tid >> 5, lane = tid & 31;
    const unsigned FULL = 0xFFFFFFFFu;
    unsigned lmask = (1u << lane) - 1u;

    float* ob = out + (size_t)b * MAXDET * 4;
    float* os = out + (size_t)NB * MAXDET * 4 + (size_t)b * MAXDET;
    float* ol = out + (size_t)NB * MAXDET * 5 + (size_t)b * MAXDET;

    if (tid == 0) { s_prefix = 0ull; s_k = TOPK; s_cnt = 0; s_actn = 0; }
    cand[tid] = 0ull;                              // zero-pad base state

    const int WD[5] = {11, 11, 10, 8, 8};
    const int SH[5] = {53, 42, 32, 8, 0};
    const int FS[5] = { 0, 53, 42, 16, 8};

    // ---- passes 0 and 1 ----
#pragma unroll 1
    for (int pass = 0; pass < 2; ++pass) {
        for (int i = tid; i < 4 * 2048; i += 1024) ((int*)hist)[i] = 0;
        __syncthreads();

        unsigned long long pfx = s_prefix;
        int shift = SH[pass];
        int sub = wid & 3;

#pragma unroll 1
        for (int ii = 0; ii < 9; ++ii) {
            int i = tid + (ii << 10);
            unsigned long long v;
            if (pass == 0) {                       // merged load + histogram
                v = (i < NANCH) ? g_key[b * NANCH + i] : 0ull;
                if (i < NANCH) key[i] = v;
            } else {
                v = (i < NANCH) ? key[i] : 0ull;
            }
            bool a = (i < NANCH) && ((pass == 0) || ((v >> 53) == pfx));
            int bin = (int)((unsigned)(v >> shift) & 2047u);
            unsigned am = __ballot_sync(FULL, a);
            if (am == FULL) {
                int b0 = __shfl_sync(FULL, bin, 0);
                if (__all_sync(FULL, bin == b0)) {
                    if (lane == 0) atomicAdd(&hist[sub][b0], 32);
                    continue;
                }
            }
            if (a) atomicAdd(&hist[sub][bin], 1);
        }
        __syncthreads();

        for (int bb = tid; bb < 2048; bb += 1024)
            hfin[bb] = hist[0][bb] + hist[1][bb] + hist[2][bb] + hist[3][bb];
        __syncthreads();

        if (tid < 32) {
            int base = lane * 64;
            int tot = 0;
            for (int e = 0; e < 64; ++e) tot += hfin[base + e];
            int suf = tot;
#pragma unroll
            for (int o = 1; o < 32; o <<= 1) {
                int v2 = __shfl_down_sync(FULL, suf, o);
                if (lane + o < 32) suf += v2;
            }
            int S = suf - tot;
            int k = s_k;
            if (k > S && k <= S + tot) {
                int S2 = S;
                for (int e = 63; e >= 0; --e) {
                    int h = hfin[base + e];
                    if (k <= S2 + h) {
                        s_prefix = (s_prefix << 11) | (unsigned long long)(base + e);
                        s_k = k - S2;
                        break;
                    }
                    S2 += h;
                }
            }
        }
        __syncthreads();
    }

    // ---- compact active set + gather sure winners ----
    {
        unsigned long long p22 = s_prefix;
#pragma unroll 1
        for (int ii = 0; ii < 9; ++ii) {
            int i = tid + (ii << 10);
            unsigned long long v = (i < NANCH) ? key[i] : 0ull;
            unsigned long long hi = v >> 42;
            bool m  = (i < NANCH) && (hi == p22);
            bool sw = (i < NANCH) && (hi > p22);
            unsigned balm = __ballot_sync(FULL, m);
            if (balm) {
                int base2 = 0;
                if (lane == 0) base2 = atomicAdd(&s_actn, __popc(balm));
                base2 = __shfl_sync(FULL, base2, 0);
                if (m) actl[base2 + __popc(balm & lmask)] = v;
            }
            unsigned balw = __ballot_sync(FULL, sw);
            if (balw) {
                int base2 = 0;
                if (lane == 0) base2 = atomicAdd(&s_cnt, __popc(balw));
                base2 = __shfl_sync(FULL, base2, 0);
                if (sw) cand[base2 + __popc(balw & lmask)] = v;
            }
        }
    }
    __syncthreads();

    int nsure = s_cnt, nact = s_actn;
    if (nsure + nact <= 1024) {
        // ---- fast path: append whole active set; sort resolves the rest ----
        if (tid < nact) cand[nsure + tid] = actl[tid];
        __syncthreads();
    } else {
        // ---- fallback: finish radix passes 2-4 + exact gather (verified) ----
#pragma unroll 1
        for (int pass = 2; pass < 5; ++pass) {
            int nb = 1 << WD[pass];
            for (int i = tid; i < 4 * 2048; i += 1024) ((int*)hist)[i] = 0;
            __syncthreads();
            unsigned long long pfx = s_prefix;
            int shift = SH[pass], fs = FS[pass];
            unsigned mask = (unsigned)(nb - 1);
            int nn = s_actn;
            int iters = (nn + 1023) >> 10;
            int sub = wid & 3;
#pragma unroll 1
            for (int ii = 0; ii < iters; ++ii) {
                int i = tid + (ii << 10);
                unsigned long long v = (i < nn) ? actl[i] : 0ull;
                bool a = (i < nn) && ((v >> fs) == pfx);
                if (a) atomicAdd(&hist[sub][(int)((unsigned)(v >> shift) & mask)], 1);
            }
            __syncthreads();
            for (int bb = tid; bb < nb; bb += 1024)
                hfin[bb] = hist[0][bb] + hist[1][bb] + hist[2][bb] + hist[3][bb];
            __syncthreads();
            if (tid < 32) {
                int bpl = nb >> 5;
                int base = lane * bpl;
                int tot = 0;
                for (int e = 0; e < bpl; ++e) tot += hfin[base + e];
                int suf = tot;
#pragma unroll
                for (int o = 1; o < 32; o <<= 1) {
                    int v2 = __shfl_down_sync(FULL, suf, o);
                    if (lane + o < 32) suf += v2;
                }
                int S = suf - tot;
                int k = s_k;
                if (k > S && k <= S + tot) {
                    int S2 = S;
                    for (int e = bpl - 1; e >= 0; --e) {
                        int h = hfin[base + e];
                        if (k <= S2 + h) {
                            unsigned long long np =
                                (s_prefix << WD[pass]) | (unsigned long long)(base + e);
                            if (pass == 2) np = (np << 16) | 0xFFFFull;
                            s_prefix = np;
                            s_k = k - S2;
                            break;
                        }
                        S2 += h;
                    }
                }
            }
            __syncthreads();
        }
        unsigned long long thr = s_prefix;
        int n2 = s_actn;
        int iters = (n2 + 1023) >> 10;
#pragma unroll 1
        for (int ii = 0; ii < iters; ++ii) {
            int i = tid + (ii << 10);
            unsigned long long v = (i < n2) ? actl[i] : 0ull;
            bool win = (i < n2) && (v >= thr);
            unsigned bal = __ballot_sync(FULL, win);
            if (bal) {
                int base2 = 0;
                if (lane == 0) base2 = atomicAdd(&s_cnt, __popc(bal));
                base2 = __shfl_sync(FULL, base2, 0);
                if (win) cand[base2 + __popc(bal & lmask)] = v;
            }
        }
        __syncthreads();
        if (tid >= TOPK) cand[tid] = 0ull;     // pad (exactly TOPK gathered)
        __syncthreads();
    }

    // ---- register bitonic sort, descending; double-buffered smem stages ----
    unsigned long long r = cand[tid];
    {
        unsigned long long* bufs[2] = { cand, actl };
        int cb = 0;
#pragma unroll 1
        for (int kk = 2; kk <= 1024; kk <<= 1) {
#pragma unroll 1
            for (int j = kk >> 1; j > 0; j >>= 1) {
                unsigned long long o;
                if (j >= 32) {
                    bufs[cb][tid] = r;
                    __syncthreads();
                    o = bufs[cb][tid ^ j];
                    cb ^= 1;
                } else {
                    o = __shfl_xor_sync(FULL, r, j);
                }
                bool up    = ((tid & kk) == 0);
                bool lower = ((tid & j) == 0);
                unsigned long long mx = (r > o) ? r : o;
                unsigned long long mn = (r > o) ? o : r;
                r = (up == lower) ? mx : mn;
            }
        }
    }
    __syncthreads();   // bufs reads done before phase-B aliases overwrite

    // ---------------- phase B: gather + per-label NMS + emit ----------------
    for (int t = tid; t < MAXDET; t += 1024) {
        ((float4*)ob)[t] = make_float4(0.f, 0.f, 0.f, 0.f);
        os[t] = 0.0f;
        ol[t] = 0.0f;
    }
    if (tid < 32) keepw[tid] = 0u;
    for (int i = tid; i < NCLS * 32; i += 1024) labmap[i] = 0u;

    int   src = 0, lb = 0;
    float sc  = 0.0f;
    if (tid < TOPK) {
        unsigned int idx = ~(unsigned int)(r & 0xFFFFFFFFull);
        src = b * NANCH + (int)idx;
        lb  = g_label[src];
        sc  = funmap((unsigned int)(r >> 32));
        float4 bx = ((const float4*)g_box)[src];
        float off = (float)lb * MAX_WH;
        float a0 = bx.x + off, a1 = bx.y + off, a2 = bx.z + off, a3 = bx.w + off;
        nx1[tid] = a0; ny1[tid] = a1; nx2[tid] = a2; ny2[tid] = a3;
        nar[tid] = (a2 - a0) * (a3 - a1);
    }
    __syncthreads();

    if (tid < TOPK)
        atomicOr(&labmap[lb * 32 + (tid >> 5)], 1u << (tid & 31));
    __syncthreads();
    if (tid < TOPK) {
        int w = tid >> 5;
        int rank = __popc(labmap[lb * 32 + w] & lmask);
        for (int ww = 0; ww < w; ++ww) rank += __popc(labmap[lb * 32 + ww]);
        if (rank < GCAP) list[lb * GCAP + rank] = (unsigned short)tid;
    }
    __syncthreads();

    const float HI = 0.7000007f;
    const float LO = 0.6999993f;

    for (int l = wid; l < NCLS; l += 32) {
        int myc = __popc(labmap[l * 32 + lane]);
#pragma unroll
        for (int o = 16; o > 0; o >>= 1)
            myc += __shfl_xor_sync(FULL, myc, o);
        int g = min(myc, GCAP);
        int base = l * GCAP;

        unsigned long long kept0 = 0ull, kept1 = 0ull;
#pragma unroll 1
        for (int m = 0; m < g; ++m) {
            int rm = list[base + m];
            float cx1 = nx1[rm], cy1 = ny1[rm], cx2 = nx2[rm], cy2 = ny2[rm];
            float ca  = nar[rm];
            bool sup = false;
#pragma unroll 1
            for (int bs = 0; bs < m; bs += 32) {
                int mi = bs + lane;
                bool valid = (mi < m) &&
                    (((mi < 64) ? (kept0 >> mi) : (kept1 >> (mi - 64))) & 1ull);
                bool s = false;
                if (valid) {
                    int ri = list[base + mi];
                    float lx = fmaxf(nx1[ri], cx1);
                    float ly = fmaxf(ny1[ri], cy1);
                    float rx = fminf(nx2[ri], cx2);
                    float ry = fminf(ny2[ri], cy2);
                    float wd = fmaxf(rx - lx, 0.0f);
                    float ht = fmaxf(ry - ly, 0.0f);
                    float inter = wd * ht;
                    float denom = nar[ri] + ca - inter + 1e-7f;
                    if (inter > HI * denom)       s = true;
                    else if (inter >= LO * denom) s = (inter / denom) > IOU_THR;
                }
                if (__ballot_sync(FULL, s)) { sup = true; break; }
            }
            if (!sup) {
                if (m < 64) kept0 |= 1ull << m; else kept1 |= 1ull << (m - 64);
                if (lane == 0) atomicOr(&keepw[rm >> 5], 1u << (rm & 31));
            }
        }
    }
    __syncthreads();

    // conf gate + block scan + scatter (kept are already score-descending)
    int f = 0;
    if (tid < TOPK)
        f = (int)((keepw[tid >> 5] >> (tid & 31)) & 1u) & (sc > CONF ? 1 : 0);
    unsigned bal = __ballot_sync(FULL, f);
    if (lane == 0) wtot[wid] = __popc(bal);
    __syncthreads();
    if (tid < 32) {
        int v = wtot[lane];
        int p = v;
#pragma unroll
        for (int o = 1; o < 32; o <<= 1) {
            int t2 = __shfl_up_sync(FULL, p, o);
            if (lane >= o) p += t2;
        }
        woff[lane] = p - v;
    }
    __syncthreads();
    int pos = woff[wid] + __popc(bal & lmask);

    if (f && pos < MAXDET) {
        ((float4*)ob)[pos] = ((const float4*)g_box)[src];
        os[pos] = sc;
        ol[pos] = (float)c_coco[lb];
    }
}

// ---------------- launch ----------------------------------------------------
extern "C" void kernel_launch(void* const* d_in, const int* in_sizes, int n_in,
                              void* d_out, int out_size) {
    (void)in_sizes; (void)n_in; (void)out_size;
    const float4* preds4 = (const float4*)d_in[0];
    float* out = (float*)d_out;

    cudaFuncSetAttribute(fused_kernel,
                         cudaFuncAttributeMaxDynamicSharedMemorySize, SEL_SMEM);

    dim3 dgrid((NQUAD * 2 + 255) / 256, NB);
    decode_kernel<<<dgrid, 256>>>(preds4);
    fused_kernel<<<NB, 1024, SEL_SMEM>>>(out);
}